// round 12
// baseline (speedup 1.0000x reference)
#include <cuda_runtime.h>
#include <cuda_fp16.h>

#define GR 16
#define NCELL 256
typedef unsigned long long ull;

// fp16 grid, per cell 12 half2 words = 3 uint4 chunks:
// packed order: [0..2]=A0 (gamma*ln_w-1), [3..5]=B0, [6..8]=A1, [9..11]=B1
__device__ uint4 g_gridq[NCELL * 3];
__device__ float g_wstage[82];

// paired-weight constant layout (float2 couples = rows 2p,2p+1):
//  [0..11] in_w pairs  [12..17] in_b pairs  [18..53] h_w pairs  [54..59] h_b pairs
//  [60..71] o_w pairs (rows 0,1)  [72..73] b_out[0..1]  [74..79] W_out[2][:]  [80] b_out[2]  [81] pad
__constant__ __align__(8) float c_wts[82];

__global__ void prep_kernel(const float* __restrict__ gamma, const float* __restrict__ beta,
                            const float* __restrict__ lnw, const float* __restrict__ lnb,
                            const float* __restrict__ w_in, const float* __restrict__ b_in,
                            const float* __restrict__ w_h,  const float* __restrict__ b_h,
                            const float* __restrict__ w_out,const float* __restrict__ b_out) {
    int idx = blockIdx.x * blockDim.x + threadIdx.x;
    if (idx < NCELL * 12) {
        int cell = idx / 12, j = idx - cell * 12;
        int l = j / 6, jj = j - l * 6;
        int isB = jj / 3, pr = jj - isB * 3;
        float v[2];
#pragma unroll
        for (int u = 0; u < 2; u++) {
            int c = 2 * pr + u;
            float g = gamma[(l * 6 + c) * NCELL + cell];
            if (isB) v[u] = beta[(l * 6 + c) * NCELL + cell] + g * lnb[l * 6 + c];
            else     v[u] = g * lnw[l * 6 + c] - 1.0f;
        }
        __half2 h = __floats2half2_rn(v[0], v[1]);
        reinterpret_cast<unsigned*>(g_gridq)[cell * 12 + j] = *reinterpret_cast<unsigned*>(&h);
    } else {
        int w = idx - NCELL * 12;
        if (w < 82) {
            float val;
            if (w < 12) {
                int q = w / 2, hi = w & 1, p = q / 2, k = q & 1;
                val = w_in[(2 * p + hi) * 2 + k];
            } else if (w < 18) {
                val = b_in[w - 12];
            } else if (w < 54) {
                int t = w - 18, q = t / 2, hi = t & 1, p = q / 6, k = q - p * 6;
                val = w_h[(2 * p + hi) * 6 + k];
            } else if (w < 60) {
                val = b_h[w - 54];
            } else if (w < 72) {
                int t = w - 60, k = t / 2, hi = t & 1;
                val = w_out[hi * 6 + k];
            } else if (w < 74) {
                val = b_out[w - 72];
            } else if (w < 80) {
                val = w_out[12 + (w - 74)];
            } else if (w == 80) {
                val = b_out[2];
            } else {
                val = 0.0f;
            }
            g_wstage[w] = val;
        }
    }
}

// ---------------- packed f32x2 helpers ----------------
__device__ __forceinline__ ull pk2(float a, float b) {
    ull r; asm("mov.b64 %0, {%1,%2};" : "=l"(r) : "f"(a), "f"(b)); return r;
}
__device__ __forceinline__ float2 upk(ull r) {
    float2 o; asm("mov.b64 {%0,%1}, %2;" : "=f"(o.x), "=f"(o.y) : "l"(r)); return o;
}
#define C2(v) pk2((v), (v))
#define FMA2(d, a, b, c) asm("fma.rn.f32x2 %0,%1,%2,%3;" : "=l"(d) : "l"(a), "l"(b), "l"(c))
#define MUL2(d, a, b)    asm("mul.rn.f32x2 %0,%1,%2;"    : "=l"(d) : "l"(a), "l"(b))
#define ADD2(d, a, b)    asm("add.rn.f32x2 %0,%1,%2;"    : "=l"(d) : "l"(a), "l"(b))

__device__ __forceinline__ ull cull(int ofs) {   // paired constant fetch (8B aligned)
    return *reinterpret_cast<const ull*>(&c_wts[ofs]);
}

// ---------------- MUFU math ----------------
__device__ __forceinline__ float mufu_ex2(float x) {
    float r; asm("ex2.approx.ftz.f32 %0, %1;" : "=f"(r) : "f"(x)); return r;
}
__device__ __forceinline__ float mufu_rcp(float x) {
    float r; asm("rcp.approx.ftz.f32 %0, %1;" : "=f"(r) : "f"(x)); return r;
}
__device__ __forceinline__ float mufu_rsqrt(float x) {
    float r; asm("rsqrt.approx.ftz.f32 %0, %1;" : "=f"(r) : "f"(x)); return r;
}

// packed silu: fma parts in f32x2, MUFU scalar
__device__ __forceinline__ ull silu2m(ull x) {
    ull y; MUL2(y, x, C2(-1.4426950408889634f));
    float2 yv = upk(y);
    ull t = pk2(mufu_ex2(yv.x), mufu_ex2(yv.y));
    ull d; ADD2(d, t, C2(1.0f));
    float2 dv = upk(d);
    ull r = pk2(mufu_rcp(dv.x), mufu_rcp(dv.y));
    ull m; MUL2(m, x, r);
    return m;
}

__device__ __forceinline__ __half2 hr(unsigned u) { return *reinterpret_cast<__half2*>(&u); }
__device__ __forceinline__ ull h2f2(__half2 v) { float2 f = __half22float2(v); return pk2(f.x, f.y); }
// f32x2 -> f16x2 (first src operand = HIGH half)
__device__ __forceinline__ __half2 f2h2(ull v) {
    float2 f = upk(v);
    unsigned r;
    asm("cvt.rn.f16x2.f32 %0, %1, %2;" : "=r"(r) : "f"(f.y), "f"(f.x));
    return hr(r);
}

// layernorm (fp32) + FiLM tail in half2; A delta-coded: h = (1+A)*t + B
__device__ __forceinline__ void modulate2h(ull& h01, ull& h23, ull& h45,
                                           __half2 A01, __half2 A23, __half2 A45,
                                           __half2 B01, __half2 B23, __half2 B45) {
    ull sp; ADD2(sp, h01, h23); ADD2(sp, sp, h45);
    float2 sv = upk(sp);
    float nmu = (sv.x + sv.y) * (-1.0f / 6.0f);
    ull nmu2 = C2(nmu);
    ull c01, c23, c45;
    ADD2(c01, h01, nmu2); ADD2(c23, h23, nmu2); ADD2(c45, h45, nmu2);
    ull q; MUL2(q, c01, c01); FMA2(q, c23, c23, q); FMA2(q, c45, c45, q);
    float2 qv = upk(q);
    float r = mufu_rsqrt(fmaf(qv.x + qv.y, 1.0f / 6.0f, 1e-5f));
    ull r2 = C2(r);
    ull t01, t23, t45;
    MUL2(t01, c01, r2); MUL2(t23, c23, r2); MUL2(t45, c45, r2);
    __half2 th01 = f2h2(t01), th23 = f2h2(t23), th45 = f2h2(t45);
    th01 = __hadd2(__hfma2(A01, th01, th01), B01);
    th23 = __hadd2(__hfma2(A23, th23, th23), B23);
    th45 = __hadd2(__hfma2(A45, th45, th45), B45);
    h01 = h2f2(th01); h23 = h2f2(th23); h45 = h2f2(th45);
}

#define CMB(dst, Aw, Bw, Cw, Dw) \
    dst = __hfma2(hr(Dw), W11, __hfma2(hr(Cw), W10, __hfma2(hr(Bw), W01, __hmul2(hr(Aw), W00))))

// process one point; sgq = 8x-replicated smem grid (uint4 view), lr = lane & 7
__device__ __forceinline__ void process_pt(const uint4* __restrict__ sgq, int lr,
                                           float px, float py,
                                           float& o0, float& o1, float& o2) {
    float fx = fminf(fmaxf(fmaf(px, 7.5f, 7.5f), 0.0f), 15.0f);
    float fy = fminf(fmaxf(fmaf(py, 7.5f, 7.5f), 0.0f), 15.0f);
    float x0f = floorf(fx), y0f = floorf(fy);
    float wx = fx - x0f, wy = fy - y0f;
    int x0 = (int)x0f, y0 = (int)y0f;
    int x1 = min(x0 + 1, GR - 1), y1 = min(y0 + 1, GR - 1);
    int i00 = ((y0 << 4) + x0) * 24 + lr;
    int i01 = ((y0 << 4) + x1) * 24 + lr;
    int i10 = ((y1 << 4) + x0) * 24 + lr;
    int i11 = ((y1 << 4) + x1) * 24 + lr;

    float w11f = wx * wy;
    __half2 W11 = __float2half2_rn(w11f);
    __half2 W01 = __float2half2_rn(wx - w11f);
    __half2 W10 = __float2half2_rn(wy - w11f);
    __half2 W00 = __float2half2_rn(1.0f - wx - wy + w11f);

    __half2 v0, v1, v2, v3, v4, v5, v6, v7, v8, v9, v10, v11;
    {
        uint4 a0 = sgq[i00], b0 = sgq[i01], c0 = sgq[i10], d0 = sgq[i11];
        CMB(v0, a0.x, b0.x, c0.x, d0.x);  CMB(v1, a0.y, b0.y, c0.y, d0.y);
        CMB(v2, a0.z, b0.z, c0.z, d0.z);  CMB(v3, a0.w, b0.w, c0.w, d0.w);
    }
    {
        uint4 a1 = sgq[i00 + 8], b1 = sgq[i01 + 8], c1 = sgq[i10 + 8], d1 = sgq[i11 + 8];
        CMB(v4, a1.x, b1.x, c1.x, d1.x);  CMB(v5, a1.y, b1.y, c1.y, d1.y);
        CMB(v6, a1.z, b1.z, c1.z, d1.z);  CMB(v7, a1.w, b1.w, c1.w, d1.w);
    }
    {
        uint4 a2 = sgq[i00 + 16], b2 = sgq[i01 + 16], c2 = sgq[i10 + 16], d2 = sgq[i11 + 16];
        CMB(v8,  a2.x, b2.x, c2.x, d2.x);  CMB(v9,  a2.y, b2.y, c2.y, d2.y);
        CMB(v10, a2.z, b2.z, c2.z, d2.z);  CMB(v11, a2.w, b2.w, c2.w, d2.w);
    }

    // input layer: packed pairs; pair p covers channels (2p, 2p+1)
    ull px2 = C2(px), py2 = C2(py);
    ull h01, h23, h45;
    {
        ull a0 = cull(12), a1 = cull(14), a2 = cull(16);
        FMA2(a0, px2, cull(0), a0);  FMA2(a0, py2, cull(2),  a0);
        FMA2(a1, px2, cull(4), a1);  FMA2(a1, py2, cull(6),  a1);
        FMA2(a2, px2, cull(8), a2);  FMA2(a2, py2, cull(10), a2);
        h01 = silu2m(a0); h23 = silu2m(a1); h45 = silu2m(a2);
    }

    modulate2h(h01, h23, h45, v0, v1, v2, v3, v4, v5);

    // hidden layer: packed matmul with duplicated activations
    {
        float2 a = upk(h01), b = upk(h23), c = upk(h45);
        ull d0 = C2(a.x), d1 = C2(a.y), d2 = C2(b.x);
        ull d3 = C2(b.y), d4 = C2(c.x), d5 = C2(c.y);
        ull acc0 = cull(54), acc1 = cull(56), acc2 = cull(58);
        FMA2(acc0, d0, cull(18), acc0); FMA2(acc0, d1, cull(20), acc0);
        FMA2(acc0, d2, cull(22), acc0); FMA2(acc0, d3, cull(24), acc0);
        FMA2(acc0, d4, cull(26), acc0); FMA2(acc0, d5, cull(28), acc0);
        FMA2(acc1, d0, cull(30), acc1); FMA2(acc1, d1, cull(32), acc1);
        FMA2(acc1, d2, cull(34), acc1); FMA2(acc1, d3, cull(36), acc1);
        FMA2(acc1, d4, cull(38), acc1); FMA2(acc1, d5, cull(40), acc1);
        FMA2(acc2, d0, cull(42), acc2); FMA2(acc2, d1, cull(44), acc2);
        FMA2(acc2, d2, cull(46), acc2); FMA2(acc2, d3, cull(48), acc2);
        FMA2(acc2, d4, cull(50), acc2); FMA2(acc2, d5, cull(52), acc2);
        h01 = silu2m(acc0); h23 = silu2m(acc1); h45 = silu2m(acc2);
    }

    modulate2h(h01, h23, h45, v6, v7, v8, v9, v10, v11);

    // output layer: channels (0,1) packed, channel 2 scalar
    {
        float2 a = upk(h01), b = upk(h23), c = upk(h45);
        ull o01 = cull(72);
        FMA2(o01, C2(a.x), cull(60), o01); FMA2(o01, C2(a.y), cull(62), o01);
        FMA2(o01, C2(b.x), cull(64), o01); FMA2(o01, C2(b.y), cull(66), o01);
        FMA2(o01, C2(c.x), cull(68), o01); FMA2(o01, C2(c.y), cull(70), o01);
        float2 ov = upk(o01);
        float s2 = c_wts[80];
        s2 = fmaf(c_wts[74], a.x, s2); s2 = fmaf(c_wts[75], a.y, s2);
        s2 = fmaf(c_wts[76], b.x, s2); s2 = fmaf(c_wts[77], b.y, s2);
        s2 = fmaf(c_wts[78], c.x, s2); s2 = fmaf(c_wts[79], c.y, s2);
        o0 = ov.x; o1 = ov.y; o2 = s2;
    }
}

// ---------------- main kernel: 512 thr/CTA (2 CTA/SM), 2 pts/thread, xy prefetch ----------------
__global__ __launch_bounds__(512, 2)
void camfield_kernel(const float4* __restrict__ xy2, float2* __restrict__ out2, int npair) {
    extern __shared__ __align__(16) uint4 sgq[];   // 768 chunks x 8 copies = 96 KB
    for (int t = threadIdx.x; t < NCELL * 3 * 8; t += blockDim.x)
        sgq[t] = g_gridq[t >> 3];
    __syncthreads();

    const int lr = threadIdx.x & 7;
    const int stride = gridDim.x * blockDim.x;
    int i = blockIdx.x * blockDim.x + threadIdx.x;
    if (i >= npair) return;
    float4 pp = xy2[i];
#pragma unroll 1
    while (true) {
        int inext = i + stride;
        float4 ppn;
        bool more = inext < npair;
        if (more) ppn = xy2[inext];          // prefetch next iteration's points

        float aa0, aa1, aa2, bb0, bb1, bb2;
        process_pt(sgq, lr, pp.x, pp.y, aa0, aa1, aa2);
        process_pt(sgq, lr, pp.z, pp.w, bb0, bb1, bb2);
        out2[3 * i + 0] = make_float2(aa0, aa1);
        out2[3 * i + 1] = make_float2(aa2, bb0);
        out2[3 * i + 2] = make_float2(bb1, bb2);

        if (!more) break;
        pp = ppn; i = inext;
    }
}

extern "C" void kernel_launch(void* const* d_in, const int* in_sizes, int n_in,
                              void* d_out, int out_size) {
    const float* xy    = (const float*)d_in[0];
    const float* gamma = (const float*)d_in[1];
    const float* beta  = (const float*)d_in[2];
    const float* w_in  = (const float*)d_in[3];
    const float* b_in  = (const float*)d_in[4];
    const float* w_h   = (const float*)d_in[5];
    const float* b_h   = (const float*)d_in[6];
    const float* w_out = (const float*)d_in[7];
    const float* b_out = (const float*)d_in[8];
    const float* ln_w  = (const float*)d_in[9];
    const float* ln_b  = (const float*)d_in[10];
    float* out = (float*)d_out;
    int n = in_sizes[0] / 2;
    int npair = n / 2;                      // N_POINTS is even

    prep_kernel<<<13, 256>>>(gamma, beta, ln_w, ln_b,
                             w_in, b_in, w_h, b_h, w_out, b_out);

    void* stage_ptr = nullptr;
    cudaGetSymbolAddress(&stage_ptr, g_wstage);
    cudaMemcpyToSymbolAsync(c_wts, stage_ptr, 82 * sizeof(float), 0,
                            cudaMemcpyDeviceToDevice);

    const int smem_bytes = NCELL * 3 * 8 * 16;   // 98304
    cudaFuncSetAttribute(camfield_kernel,
                         cudaFuncAttributeMaxDynamicSharedMemorySize, smem_bytes);
    camfield_kernel<<<296, 512, smem_bytes>>>((const float4*)xy, (float2*)out, npair);
}

// round 13
// speedup vs baseline: 1.4298x; 1.4298x over previous
#include <cuda_runtime.h>
#include <cuda_fp16.h>

#define GR 16
#define NCELL 256
typedef unsigned long long ull;

// fp16 grid, per cell 12 half2 words = 3 uint4 chunks:
// packed order: [0..2]=A0 (gamma*ln_w-1), [3..5]=B0, [6..8]=A1, [9..11]=B1
__device__ uint4 g_gridq[NCELL * 3];
__device__ float g_wstage[82];

// paired-weight constant layout (float2 couples = rows 2p,2p+1):
//  [0..11] in_w pairs  [12..17] in_b pairs  [18..53] h_w pairs  [54..59] h_b pairs
//  [60..71] o_w pairs (rows 0,1)  [72..73] b_out[0..1]  [74..79] W_out[2][:]  [80] b_out[2]  [81] pad
__constant__ __align__(8) float c_wts[82];

__global__ void prep_kernel(const float* __restrict__ gamma, const float* __restrict__ beta,
                            const float* __restrict__ lnw, const float* __restrict__ lnb,
                            const float* __restrict__ w_in, const float* __restrict__ b_in,
                            const float* __restrict__ w_h,  const float* __restrict__ b_h,
                            const float* __restrict__ w_out,const float* __restrict__ b_out) {
    int idx = blockIdx.x * blockDim.x + threadIdx.x;
    if (idx < NCELL * 12) {
        int cell = idx / 12, j = idx - cell * 12;
        int l = j / 6, jj = j - l * 6;
        int isB = jj / 3, pr = jj - isB * 3;
        float v[2];
#pragma unroll
        for (int u = 0; u < 2; u++) {
            int c = 2 * pr + u;
            float g = gamma[(l * 6 + c) * NCELL + cell];
            if (isB) v[u] = beta[(l * 6 + c) * NCELL + cell] + g * lnb[l * 6 + c];
            else     v[u] = g * lnw[l * 6 + c] - 1.0f;
        }
        __half2 h = __floats2half2_rn(v[0], v[1]);
        reinterpret_cast<unsigned*>(g_gridq)[cell * 12 + j] = *reinterpret_cast<unsigned*>(&h);
    } else {
        int w = idx - NCELL * 12;
        if (w < 82) {
            float val;
            if (w < 12) {
                int q = w / 2, hi = w & 1, p = q / 2, k = q & 1;
                val = w_in[(2 * p + hi) * 2 + k];
            } else if (w < 18) {
                val = b_in[w - 12];
            } else if (w < 54) {
                int t = w - 18, q = t / 2, hi = t & 1, p = q / 6, k = q - p * 6;
                val = w_h[(2 * p + hi) * 6 + k];
            } else if (w < 60) {
                val = b_h[w - 54];
            } else if (w < 72) {
                int t = w - 60, k = t / 2, hi = t & 1;
                val = w_out[hi * 6 + k];
            } else if (w < 74) {
                val = b_out[w - 72];
            } else if (w < 80) {
                val = w_out[12 + (w - 74)];
            } else if (w == 80) {
                val = b_out[2];
            } else {
                val = 0.0f;
            }
            g_wstage[w] = val;
        }
    }
}

// ---------------- packed f32x2 helpers ----------------
__device__ __forceinline__ ull pk2(float a, float b) {
    ull r; asm("mov.b64 %0, {%1,%2};" : "=l"(r) : "f"(a), "f"(b)); return r;
}
__device__ __forceinline__ float2 upk(ull r) {
    float2 o; asm("mov.b64 {%0,%1}, %2;" : "=f"(o.x), "=f"(o.y) : "l"(r)); return o;
}
#define C2(v) pk2((v), (v))
#define FMA2(d, a, b, c) asm("fma.rn.f32x2 %0,%1,%2,%3;" : "=l"(d) : "l"(a), "l"(b), "l"(c))
#define MUL2(d, a, b)    asm("mul.rn.f32x2 %0,%1,%2;"    : "=l"(d) : "l"(a), "l"(b))
#define ADD2(d, a, b)    asm("add.rn.f32x2 %0,%1,%2;"    : "=l"(d) : "l"(a), "l"(b))

__device__ __forceinline__ ull cull(int ofs) {   // paired constant fetch (8B aligned)
    return *reinterpret_cast<const ull*>(&c_wts[ofs]);
}

// ---------------- MUFU math ----------------
__device__ __forceinline__ float mufu_ex2(float x) {
    float r; asm("ex2.approx.ftz.f32 %0, %1;" : "=f"(r) : "f"(x)); return r;
}
__device__ __forceinline__ float mufu_rcp(float x) {
    float r; asm("rcp.approx.ftz.f32 %0, %1;" : "=f"(r) : "f"(x)); return r;
}
__device__ __forceinline__ float mufu_rsqrt(float x) {
    float r; asm("rsqrt.approx.ftz.f32 %0, %1;" : "=f"(r) : "f"(x)); return r;
}

// packed silu: fma parts in f32x2, MUFU scalar
__device__ __forceinline__ ull silu2m(ull x) {
    ull y; MUL2(y, x, C2(-1.4426950408889634f));
    float2 yv = upk(y);
    ull t = pk2(mufu_ex2(yv.x), mufu_ex2(yv.y));
    ull d; ADD2(d, t, C2(1.0f));
    float2 dv = upk(d);
    ull r = pk2(mufu_rcp(dv.x), mufu_rcp(dv.y));
    ull m; MUL2(m, x, r);
    return m;
}

__device__ __forceinline__ __half2 hr(unsigned u) { return *reinterpret_cast<__half2*>(&u); }
__device__ __forceinline__ ull h2f2(__half2 v) { float2 f = __half22float2(v); return pk2(f.x, f.y); }

// layernorm + FiLM, parallel-moments form (short critical path):
//   Sh = sum(h), Sq = sum(h^2) computed concurrently;
//   var = E[h^2] - mu^2; while rsqrt runs, c = h - mu and cc = c + A*c;
//   h' = cc * r + B   (A delta-coded)
__device__ __forceinline__ void modulate2(ull& h01, ull& h23, ull& h45,
                                          ull A01, ull A23, ull A45,
                                          ull B01, ull B23, ull B45) {
    ull sp; ADD2(sp, h01, h23); ADD2(sp, sp, h45);
    ull q;  MUL2(q, h01, h01); FMA2(q, h23, h23, q); FMA2(q, h45, h45, q);
    float2 sv = upk(sp);
    float2 qv = upk(q);
    float mu = (sv.x + sv.y) * (1.0f / 6.0f);
    float ms = (qv.x + qv.y) * (1.0f / 6.0f);
    float var = fmaf(-mu, mu, ms);
    float r = mufu_rsqrt(var + 1e-5f);
    ull nmu2 = C2(-mu);
    ull c01, c23, c45;
    ADD2(c01, h01, nmu2); ADD2(c23, h23, nmu2); ADD2(c45, h45, nmu2);
    ull cc01, cc23, cc45;                      // (1+A)*c, overlaps rsqrt latency
    FMA2(cc01, A01, c01, c01); FMA2(cc23, A23, c23, c23); FMA2(cc45, A45, c45, c45);
    ull r2 = C2(r);
    FMA2(h01, cc01, r2, B01); FMA2(h23, cc23, r2, B23); FMA2(h45, cc45, r2, B45);
}

#define CMB(dst, Aw, Bw, Cw, Dw) \
    dst = __hfma2(hr(Dw), W11, __hfma2(hr(Cw), W10, __hfma2(hr(Bw), W01, __hmul2(hr(Aw), W00))))

// process one point; sgq = 8x-replicated smem grid (uint4 view), lr = lane & 7
__device__ __forceinline__ void process_pt(const uint4* __restrict__ sgq, int lr,
                                           float px, float py,
                                           float& o0, float& o1, float& o2) {
    float fx = fminf(fmaxf(fmaf(px, 7.5f, 7.5f), 0.0f), 15.0f);
    float fy = fminf(fmaxf(fmaf(py, 7.5f, 7.5f), 0.0f), 15.0f);
    float x0f = floorf(fx), y0f = floorf(fy);
    float wx = fx - x0f, wy = fy - y0f;
    int x0 = (int)x0f, y0 = (int)y0f;
    int x1 = min(x0 + 1, GR - 1), y1 = min(y0 + 1, GR - 1);
    int i00 = ((y0 << 4) + x0) * 24 + lr;
    int i01 = ((y0 << 4) + x1) * 24 + lr;
    int i10 = ((y1 << 4) + x0) * 24 + lr;
    int i11 = ((y1 << 4) + x1) * 24 + lr;

    float w11f = wx * wy;
    __half2 W11 = __float2half2_rn(w11f);
    __half2 W01 = __float2half2_rn(wx - w11f);
    __half2 W10 = __float2half2_rn(wy - w11f);
    __half2 W00 = __float2half2_rn(1.0f - wx - wy + w11f);

    __half2 v0, v1, v2, v3, v4, v5, v6, v7, v8, v9, v10, v11;
    {
        uint4 a0 = sgq[i00], b0 = sgq[i01], c0 = sgq[i10], d0 = sgq[i11];
        CMB(v0, a0.x, b0.x, c0.x, d0.x);  CMB(v1, a0.y, b0.y, c0.y, d0.y);
        CMB(v2, a0.z, b0.z, c0.z, d0.z);  CMB(v3, a0.w, b0.w, c0.w, d0.w);
    }
    {
        uint4 a1 = sgq[i00 + 8], b1 = sgq[i01 + 8], c1 = sgq[i10 + 8], d1 = sgq[i11 + 8];
        CMB(v4, a1.x, b1.x, c1.x, d1.x);  CMB(v5, a1.y, b1.y, c1.y, d1.y);
        CMB(v6, a1.z, b1.z, c1.z, d1.z);  CMB(v7, a1.w, b1.w, c1.w, d1.w);
    }
    {
        uint4 a2 = sgq[i00 + 16], b2 = sgq[i01 + 16], c2 = sgq[i10 + 16], d2 = sgq[i11 + 16];
        CMB(v8,  a2.x, b2.x, c2.x, d2.x);  CMB(v9,  a2.y, b2.y, c2.y, d2.y);
        CMB(v10, a2.z, b2.z, c2.z, d2.z);  CMB(v11, a2.w, b2.w, c2.w, d2.w);
    }

    // input layer: packed pairs; pair p covers channels (2p, 2p+1)
    ull px2 = C2(px), py2 = C2(py);
    ull h01, h23, h45;
    {
        ull a0 = cull(12), a1 = cull(14), a2 = cull(16);
        FMA2(a0, px2, cull(0), a0);  FMA2(a0, py2, cull(2),  a0);
        FMA2(a1, px2, cull(4), a1);  FMA2(a1, py2, cull(6),  a1);
        FMA2(a2, px2, cull(8), a2);  FMA2(a2, py2, cull(10), a2);
        h01 = silu2m(a0); h23 = silu2m(a1); h45 = silu2m(a2);
    }

    modulate2(h01, h23, h45, h2f2(v0), h2f2(v1), h2f2(v2),
                             h2f2(v3), h2f2(v4), h2f2(v5));

    // hidden layer: packed matmul with duplicated activations
    {
        float2 a = upk(h01), b = upk(h23), c = upk(h45);
        ull d0 = C2(a.x), d1 = C2(a.y), d2 = C2(b.x);
        ull d3 = C2(b.y), d4 = C2(c.x), d5 = C2(c.y);
        ull acc0 = cull(54), acc1 = cull(56), acc2 = cull(58);
        FMA2(acc0, d0, cull(18), acc0); FMA2(acc0, d1, cull(20), acc0);
        FMA2(acc0, d2, cull(22), acc0); FMA2(acc0, d3, cull(24), acc0);
        FMA2(acc0, d4, cull(26), acc0); FMA2(acc0, d5, cull(28), acc0);
        FMA2(acc1, d0, cull(30), acc1); FMA2(acc1, d1, cull(32), acc1);
        FMA2(acc1, d2, cull(34), acc1); FMA2(acc1, d3, cull(36), acc1);
        FMA2(acc1, d4, cull(38), acc1); FMA2(acc1, d5, cull(40), acc1);
        FMA2(acc2, d0, cull(42), acc2); FMA2(acc2, d1, cull(44), acc2);
        FMA2(acc2, d2, cull(46), acc2); FMA2(acc2, d3, cull(48), acc2);
        FMA2(acc2, d4, cull(50), acc2); FMA2(acc2, d5, cull(52), acc2);
        h01 = silu2m(acc0); h23 = silu2m(acc1); h45 = silu2m(acc2);
    }

    modulate2(h01, h23, h45, h2f2(v6), h2f2(v7), h2f2(v8),
                             h2f2(v9), h2f2(v10), h2f2(v11));

    // output layer: channels (0,1) packed, channel 2 scalar
    {
        float2 a = upk(h01), b = upk(h23), c = upk(h45);
        ull o01 = cull(72);
        FMA2(o01, C2(a.x), cull(60), o01); FMA2(o01, C2(a.y), cull(62), o01);
        FMA2(o01, C2(b.x), cull(64), o01); FMA2(o01, C2(b.y), cull(66), o01);
        FMA2(o01, C2(c.x), cull(68), o01); FMA2(o01, C2(c.y), cull(70), o01);
        float2 ov = upk(o01);
        float s2 = c_wts[80];
        s2 = fmaf(c_wts[74], a.x, s2); s2 = fmaf(c_wts[75], a.y, s2);
        s2 = fmaf(c_wts[76], b.x, s2); s2 = fmaf(c_wts[77], b.y, s2);
        s2 = fmaf(c_wts[78], c.x, s2); s2 = fmaf(c_wts[79], c.y, s2);
        o0 = ov.x; o1 = ov.y; o2 = s2;
    }
}

// ---------------- main kernel: 512 thr/CTA (2 CTA/SM), 2 pts/thread, 8x replicated smem ----------------
__global__ __launch_bounds__(512, 2)
void camfield_kernel(const float4* __restrict__ xy2, float2* __restrict__ out2, int npair) {
    extern __shared__ __align__(16) uint4 sgq[];   // 768 chunks x 8 copies = 96 KB
    for (int t = threadIdx.x; t < NCELL * 3 * 8; t += blockDim.x)
        sgq[t] = g_gridq[t >> 3];
    __syncthreads();

    const int lr = threadIdx.x & 7;
    const int stride = gridDim.x * blockDim.x;
#pragma unroll 1
    for (int i = blockIdx.x * blockDim.x + threadIdx.x; i < npair; i += stride) {
        float4 pp = xy2[i];                 // points 2i, 2i+1
        float aa0, aa1, aa2, bb0, bb1, bb2;
        process_pt(sgq, lr, pp.x, pp.y, aa0, aa1, aa2);
        process_pt(sgq, lr, pp.z, pp.w, bb0, bb1, bb2);
        out2[3 * i + 0] = make_float2(aa0, aa1);
        out2[3 * i + 1] = make_float2(aa2, bb0);
        out2[3 * i + 2] = make_float2(bb1, bb2);
    }
}

extern "C" void kernel_launch(void* const* d_in, const int* in_sizes, int n_in,
                              void* d_out, int out_size) {
    const float* xy    = (const float*)d_in[0];
    const float* gamma = (const float*)d_in[1];
    const float* beta  = (const float*)d_in[2];
    const float* w_in  = (const float*)d_in[3];
    const float* b_in  = (const float*)d_in[4];
    const float* w_h   = (const float*)d_in[5];
    const float* b_h   = (const float*)d_in[6];
    const float* w_out = (const float*)d_in[7];
    const float* b_out = (const float*)d_in[8];
    const float* ln_w  = (const float*)d_in[9];
    const float* ln_b  = (const float*)d_in[10];
    float* out = (float*)d_out;
    int n = in_sizes[0] / 2;
    int npair = n / 2;                      // N_POINTS is even

    prep_kernel<<<13, 256>>>(gamma, beta, ln_w, ln_b,
                             w_in, b_in, w_h, b_h, w_out, b_out);

    void* stage_ptr = nullptr;
    cudaGetSymbolAddress(&stage_ptr, g_wstage);
    cudaMemcpyToSymbolAsync(c_wts, stage_ptr, 82 * sizeof(float), 0,
                            cudaMemcpyDeviceToDevice);

    const int smem_bytes = NCELL * 3 * 8 * 16;   // 98304
    cudaFuncSetAttribute(camfield_kernel,
                         cudaFuncAttributeMaxDynamicSharedMemorySize, smem_bytes);
    camfield_kernel<<<296, 512, smem_bytes>>>((const float4*)xy, (float2*)out, npair);
}